// round 13
// baseline (speedup 1.0000x reference)
#include <cuda_runtime.h>
#include <math.h>

#define Bb 4
#define DM 192
#define DI 384
#define Hh 48
#define Ww 48
#define Ll 2304
#define Kk 4
#define Nn 16
#define Rr 12
#define Cc 44   // R + 2N
#define Gc 24   // scan chunks
#define CL 96   // chunk length = Ll/Gc (multiple of 48)

// ---------------- scratch (static __device__, no allocation) ----------------
__device__ float g_xc  [(size_t)Bb*DI*Ll];        // (B, D, L)  pre-conv x branch
__device__ float g_xcT [(size_t)Bb*Ll*DI];        // (B, L, D)  post conv+gelu (row-major order)
__device__ float g_u1  [(size_t)Bb*Ll*DI];        // (B, L1,D)  same, column-major scan order
__device__ float g_z1t [(size_t)Bb*Ll*DI];        // (B, L, D)  gelu(z)
__device__ float g_dts [(size_t)Bb*Kk*Ll*Rr];     // (B,K,L,12)
__device__ float g_B   [(size_t)Bb*Kk*Ll*Nn];     // (B,K,L,N)
__device__ float g_C   [(size_t)Bb*Kk*Ll*Nn];     // (B,K,L,N)
__device__ float g_dlt [(size_t)Bb*Kk*DI*Ll];     // (B,K,D,L)  softplus delta
__device__ float g_ysT [(size_t)Bb*Kk*Ll*DI];     // (B,K,L,D)  scan outputs (+D*u)
__device__ float g_g   [(size_t)Bb*Ll*DI];        // (B, L, D)  gated, pre out_proj
__device__ float2 g_PF [(size_t)Bb*Kk*DI*Nn*Gc];  // (bk,d,n,c) chunk (P, F)
__device__ float g_hin [(size_t)Bb*Kk*DI*Nn*Gc];  // (bk,d,n,c) chunk incoming h

__device__ __forceinline__ float gelu_exact(float x) {
    return 0.5f * x * (1.0f + erff(x * 0.7071067811865476f));
}

// raw MUFU.EX2
__device__ __forceinline__ float ex2(float x) {
    float y;
    asm("ex2.approx.f32 %0, %1;" : "=f"(y) : "f"(x));
    return y;
}

// ---- packed fp32x2 helpers (sm_10x FFMA2) ----
__device__ __forceinline__ unsigned long long pack2(float lo, float hi) {
    unsigned long long r;
    asm("mov.b64 %0, {%1, %2};" : "=l"(r) : "f"(lo), "f"(hi));
    return r;
}
__device__ __forceinline__ void unpack2(unsigned long long v, float& lo, float& hi) {
    asm("mov.b64 {%0, %1}, %2;" : "=f"(lo), "=f"(hi) : "l"(v));
}
__device__ __forceinline__ void ffma2(unsigned long long& d, unsigned long long a,
                                      unsigned long long b) {
    asm("fma.rn.f32x2 %0, %1, %2, %3;" : "=l"(d) : "l"(a), "l"(b), "l"(d));
}

// ---------------- 1) in_proj GEMM 64x256x(K=192), 8x8/thread, FFMA2 ---------
__global__ __launch_bounds__(256) void gemm_inproj(const float* __restrict__ W,
                                                   const float* __restrict__ x) {
    __shared__ float As[16][68];
    __shared__ float Bs[16][260];
    int b = blockIdx.z;
    int mBase = blockIdx.y * 64;
    int nBase = blockIdx.x * 256;
    int tid = threadIdx.x;
    int tm = (tid >> 5) * 8;
    int tn4 = (tid & 31) * 4;

    unsigned long long acc2[8][4];
#pragma unroll
    for (int i = 0; i < 8; i++)
#pragma unroll
        for (int j = 0; j < 4; j++) acc2[i][j] = 0ULL;

    for (int k0 = 0; k0 < 192; k0 += 16) {
#pragma unroll
        for (int t = 0; t < 4; t++) {
            int i = tid + t * 256;
            int r = i >> 4, c = i & 15;
            As[c][r] = W[(mBase + r) * 192 + k0 + c];
        }
#pragma unroll
        for (int t = 0; t < 16; t++) {
            int i = tid + t * 256;
            int r = i >> 8, n = i & 255;
            Bs[r][n] = x[((size_t)b * 192 + (k0 + r)) * Ll + nBase + n];
        }
        __syncthreads();
#pragma unroll
        for (int kk = 0; kk < 16; kk++) {
            float4 a0 = *reinterpret_cast<const float4*>(&As[kk][tm]);
            float4 a1 = *reinterpret_cast<const float4*>(&As[kk][tm + 4]);
            ulonglong2 bq0 = *reinterpret_cast<const ulonglong2*>(&Bs[kk][tn4]);
            ulonglong2 bq1 = *reinterpret_cast<const ulonglong2*>(&Bs[kk][tn4 + 128]);
            unsigned long long ap[8];
            ap[0] = pack2(a0.x, a0.x); ap[1] = pack2(a0.y, a0.y);
            ap[2] = pack2(a0.z, a0.z); ap[3] = pack2(a0.w, a0.w);
            ap[4] = pack2(a1.x, a1.x); ap[5] = pack2(a1.y, a1.y);
            ap[6] = pack2(a1.z, a1.z); ap[7] = pack2(a1.w, a1.w);
            unsigned long long bp[4] = {bq0.x, bq0.y, bq1.x, bq1.y};
#pragma unroll
            for (int i = 0; i < 8; i++)
#pragma unroll
                for (int j = 0; j < 4; j++) ffma2(acc2[i][j], ap[i], bp[j]);
        }
        __syncthreads();
    }
    float acc[8][8];
#pragma unroll
    for (int i = 0; i < 8; i++) {
        unpack2(acc2[i][0], acc[i][0], acc[i][1]);
        unpack2(acc2[i][1], acc[i][2], acc[i][3]);
        unpack2(acc2[i][2], acc[i][4], acc[i][5]);
        unpack2(acc2[i][3], acc[i][6], acc[i][7]);
    }
    if (mBase < DI) {   // x branch -> g_xc (B, D, L)
#pragma unroll
        for (int i = 0; i < 8; i++) {
            int o = mBase + tm + i;
            float* row = &g_xc[((size_t)b * DI + o) * Ll + nBase];
            *reinterpret_cast<float4*>(&row[tn4]) =
                make_float4(acc[i][0], acc[i][1], acc[i][2], acc[i][3]);
            *reinterpret_cast<float4*>(&row[tn4 + 128]) =
                make_float4(acc[i][4], acc[i][5], acc[i][6], acc[i][7]);
        }
    } else {            // z branch -> gelu -> g_z1t (B, L, D)
        int oz = mBase - DI + tm;
#pragma unroll
        for (int j = 0; j < 8; j++) {
            int l = nBase + ((j < 4) ? (tn4 + j) : (128 + tn4 + j - 4));
            float* row = &g_z1t[((size_t)b * Ll + l) * DI + oz];
            *reinterpret_cast<float4*>(row) = make_float4(
                gelu_exact(acc[0][j]), gelu_exact(acc[1][j]),
                gelu_exact(acc[2][j]), gelu_exact(acc[3][j]));
            *reinterpret_cast<float4*>(row + 4) = make_float4(
                gelu_exact(acc[4][j]), gelu_exact(acc[5][j]),
                gelu_exact(acc[6][j]), gelu_exact(acc[7][j]));
        }
    }
}

// ---------------- 2) depthwise 3x3 conv, row-tiled, coalesced IO -------------
__global__ void conv_dw(const float* __restrict__ cw, const float* __restrict__ cb) {
    __shared__ float s[16][145];
    int b = blockIdx.z;
    int d0 = blockIdx.y * 16;
    int h = blockIdx.x;
    int t = threadIdx.x;  // 256

    for (int i = t; i < 16 * 144; i += 256) {
        int d = i / 144, j = i % 144;
        int r = j / 48;
        int hh = h + r - 1;
        float v = 0.f;
        if (hh >= 0 && hh < 48)
            v = g_xc[((size_t)b * DI + d0 + d) * Ll + hh * 48 + (j - r * 48)];
        s[d][j] = v;
    }
    __syncthreads();

    int d = t & 15, w0 = t >> 4;
    float wr[9];
#pragma unroll
    for (int i = 0; i < 9; i++) wr[i] = cw[(d0 + d) * 9 + i];
    float bias = cb[d0 + d];

#pragma unroll
    for (int wi = 0; wi < 3; wi++) {
        int w = w0 + wi * 16;
        float acc = bias;
#pragma unroll
        for (int dh = 0; dh < 3; dh++)
#pragma unroll
            for (int dw = 0; dw < 3; dw++) {
                int ww = w + dw - 1;
                if (ww >= 0 && ww < 48)
                    acc = fmaf(wr[dh * 3 + dw], s[d][dh * 48 + ww], acc);
            }
        float v = gelu_exact(acc);
        g_xcT[((size_t)b * Ll + h * 48 + w) * DI + d0 + d] = v;
        g_u1 [((size_t)b * Ll + w * 48 + h) * DI + d0 + d] = v;
    }
}

// ---------------- 3) x_dbl GEMM: (44 x 2304) = W_k(44x384) @ xs[bk], FFMA2 ---
__global__ void xdbl_kernel(const float* __restrict__ xpw) {
    __shared__ float Ws[32][49];
    __shared__ float Xs[32][68];
    int bk = blockIdx.y;
    int b = bk >> 2, k = bk & 3;
    int l0 = blockIdx.x * 64;
    int tid = threadIdx.x;
    int tc = (tid >> 4) * 3;
    int tl = (tid & 15) * 4;

    const float* ubase = ((k & 1) ? g_u1 : g_xcT) + (size_t)b * Ll * DI;

    unsigned long long acc2[3][2];
#pragma unroll
    for (int i = 0; i < 3; i++) { acc2[i][0] = 0ULL; acc2[i][1] = 0ULL; }

    if (tid < 128) {
        int kd = tid & 31, c = 44 + (tid >> 5);
        Ws[kd][c] = 0.f;
    }
    __syncthreads();

    for (int k0 = 0; k0 < DI; k0 += 32) {
        for (int i = tid; i < 44 * 32; i += 256) {
            int c = i >> 5, kd = i & 31;
            Ws[kd][c] = xpw[((size_t)(k * Cc + c)) * DI + k0 + kd];
        }
#pragma unroll
        for (int t = 0; t < 2; t++) {
            int q = tid + t * 256;
            int l = q >> 3, kq = (q & 7) * 4;
            int row = (k < 2) ? (l0 + l) : (2303 - (l0 + l));
            float4 v = *reinterpret_cast<const float4*>(&ubase[(size_t)row * DI + k0 + kq]);
            Xs[kq][l] = v.x; Xs[kq + 1][l] = v.y;
            Xs[kq + 2][l] = v.z; Xs[kq + 3][l] = v.w;
        }
        __syncthreads();
#pragma unroll
        for (int kd = 0; kd < 32; kd++) {
            unsigned long long ap0 = pack2(Ws[kd][tc], Ws[kd][tc]);
            unsigned long long ap1 = pack2(Ws[kd][tc + 1], Ws[kd][tc + 1]);
            unsigned long long ap2 = pack2(Ws[kd][tc + 2], Ws[kd][tc + 2]);
            ulonglong2 bq = *reinterpret_cast<const ulonglong2*>(&Xs[kd][tl]);
            ffma2(acc2[0][0], ap0, bq.x); ffma2(acc2[0][1], ap0, bq.y);
            ffma2(acc2[1][0], ap1, bq.x); ffma2(acc2[1][1], ap1, bq.y);
            ffma2(acc2[2][0], ap2, bq.x); ffma2(acc2[2][1], ap2, bq.y);
        }
        __syncthreads();
    }
    float acc[3][4];
#pragma unroll
    for (int r = 0; r < 3; r++) {
        unpack2(acc2[r][0], acc[r][0], acc[r][1]);
        unpack2(acc2[r][1], acc[r][2], acc[r][3]);
    }
#pragma unroll
    for (int r = 0; r < 3; r++) {
        int c = tc + r;
        if (c < 12) {
#pragma unroll
            for (int j = 0; j < 4; j++)
                g_dts[((size_t)bk * Ll + l0 + tl + j) * Rr + c] = acc[r][j];
        } else if (c < 28) {
#pragma unroll
            for (int j = 0; j < 4; j++)
                g_B[((size_t)bk * Ll + l0 + tl + j) * Nn + (c - 12)] = acc[r][j];
        } else if (c < Cc) {
#pragma unroll
            for (int j = 0; j < 4; j++)
                g_C[((size_t)bk * Ll + l0 + tl + j) * Nn + (c - 28)] = acc[r][j];
        }
    }
}

// ---------------- 4) delta = softplus(dtw @ dts + bias) -> (bk, d, L) --------
__global__ void delta_kernel(const float* __restrict__ dtw, const float* __restrict__ dtb) {
    __shared__ float dts_s[16][12];
    __shared__ float stage[384 * 16 + 224];
    int bk = blockIdx.y;
    int k = bk & 3;
    int l0 = blockIdx.x * 16;
    int d = threadIdx.x;   // 384 threads

    if (threadIdx.x < 192) {
        int l = threadIdx.x / 12, r = threadIdx.x % 12;
        dts_s[l][r] = g_dts[((size_t)bk * Ll + l0 + l) * Rr + r];
    }
    float w[12];
    {
        const float4* wp = reinterpret_cast<const float4*>(dtw + ((size_t)k * DI + d) * Rr);
        float4 a = wp[0], bq = wp[1], cq = wp[2];
        w[0]=a.x; w[1]=a.y; w[2]=a.z; w[3]=a.w;
        w[4]=bq.x; w[5]=bq.y; w[6]=bq.z; w[7]=bq.w;
        w[8]=cq.x; w[9]=cq.y; w[10]=cq.z; w[11]=cq.w;
    }
    float bias = dtb[k * DI + d];
    __syncthreads();

#pragma unroll
    for (int l = 0; l < 16; l++) {
        float acc = bias;
#pragma unroll
        for (int r = 0; r < Rr; r++) acc = fmaf(w[r], dts_s[l][r], acc);
        float sp = (acc > 15.f) ? acc : __logf(1.f + __expf(acc));
        stage[d * 16 + l + (d >> 1)] = sp;
    }
    __syncthreads();
    int lw = threadIdx.x & 15;
    int dw0 = threadIdx.x >> 4;
#pragma unroll
    for (int i = 0; i < 16; i++) {
        int dd = dw0 + 24 * i;
        g_dlt[((size_t)bk * DI + dd) * Ll + l0 + lw] = stage[dd * 16 + lw + (dd >> 1)];
    }
}

// ---------------- 5a) scan pass A: 4-lane x 4-state; (P, F); batched loads ---
__global__ void scan_passA(const float* __restrict__ Alogs) {
    int bk = blockIdx.y;
    int b = bk >> 2, k = bk & 3;
    int wid = threadIdx.x >> 5, lane = threadIdx.x & 31;
    int dsub = lane >> 2, nq = lane & 3;
    int d = blockIdx.x * 64 + wid * 8 + dsub;
    int c = blockIdx.z;

    float a2[4], h[4] = {0.f, 0.f, 0.f, 0.f}, P[4] = {1.f, 1.f, 1.f, 1.f};
#pragma unroll
    for (int i = 0; i < 4; i++)
        a2[i] = -__expf(Alogs[((size_t)k * DI + d) * Nn + 4 * nq + i]) * 1.4426950408889634f;

    const float4* dp = reinterpret_cast<const float4*>(g_dlt + ((size_t)bk * DI + d) * Ll + c * CL);
    const float4* Bq = reinterpret_cast<const float4*>(g_B + ((size_t)bk * Ll + c * CL) * Nn + 4 * nq);
    const float* ubase = ((k & 1) ? g_u1 : g_xcT) + (size_t)b * Ll * DI + d;
    const float* up;
    int ustep;
    if (k < 2) { up = ubase + (size_t)(c * CL) * DI;          ustep = DI;  }
    else       { up = ubase + (size_t)(2303 - c * CL) * DI;   ustep = -DI; }

    for (int t = 0; t < CL / 16; t++) {
        float ur[16];
#pragma unroll
        for (int j = 0; j < 16; j++) ur[j] = up[(long)j * ustep];
        up += (long)16 * ustep;
#pragma unroll
        for (int q = 0; q < 4; q++) {
            float4 dv = dp[q];
            float dvv[4] = {dv.x, dv.y, dv.z, dv.w};
#pragma unroll
            for (int jj = 0; jj < 4; jj++) {
                int j = q * 4 + jj;
                float delta = dvv[jj];
                float4 Bv = Bq[j * 4];
                float du = delta * ur[j];
                float dA;
                dA = ex2(delta * a2[0]); h[0] = fmaf(h[0], dA, du * Bv.x); P[0] *= dA;
                dA = ex2(delta * a2[1]); h[1] = fmaf(h[1], dA, du * Bv.y); P[1] *= dA;
                dA = ex2(delta * a2[2]); h[2] = fmaf(h[2], dA, du * Bv.z); P[2] *= dA;
                dA = ex2(delta * a2[3]); h[3] = fmaf(h[3], dA, du * Bv.w); P[3] *= dA;
            }
        }
        dp += 4;
        Bq += 64;
    }
#pragma unroll
    for (int i = 0; i < 4; i++)
        g_PF[(((size_t)bk * DI + d) * Nn + 4 * nq + i) * Gc + c] = make_float2(P[i], h[i]);
}

// ---------------- 5b) fixup: sequential combine over chunks ------------------
__global__ void scan_fixup() {
    int t = blockIdx.x * 256 + threadIdx.x;   // over 16*384*16 = 98304
    size_t base = (size_t)t * Gc;
    float h = 0.f;
#pragma unroll
    for (int c = 0; c < Gc; c++) {
        g_hin[base + c] = h;
        float2 pf = g_PF[base + c];
        h = fmaf(pf.x, h, pf.y);
    }
}

// ---------------- 5c) scan pass B: 4-lane x 4-state, seeded; batched loads ---
__global__ void scan_passB(const float* __restrict__ Alogs, const float* __restrict__ Ds) {
    __shared__ float sy[16][65];
    int bk = blockIdx.y;
    int b = bk >> 2, k = bk & 3;
    int tid = threadIdx.x;
    int wid = tid >> 5, lane = tid & 31;
    int dsub = lane >> 2, nq = lane & 3;
    int d = blockIdx.x * 64 + wid * 8 + dsub;
    int c = blockIdx.z;

    float a2[4], h[4], yk[4];
#pragma unroll
    for (int i = 0; i < 4; i++) {
        a2[i] = -__expf(Alogs[((size_t)k * DI + d) * Nn + 4 * nq + i]) * 1.4426950408889634f;
        h[i] = g_hin[(((size_t)bk * DI + d) * Nn + 4 * nq + i) * Gc + c];
    }
    float Dd = Ds[k * DI + d];

    const float4* dp = reinterpret_cast<const float4*>(g_dlt + ((size_t)bk * DI + d) * Ll + c * CL);
    const float4* Bq = reinterpret_cast<const float4*>(g_B + ((size_t)bk * Ll + c * CL) * Nn + 4 * nq);
    const float4* Cq = reinterpret_cast<const float4*>(g_C + ((size_t)bk * Ll + c * CL) * Nn + 4 * nq);
    const float* ubase = ((k & 1) ? g_u1 : g_xcT) + (size_t)b * Ll * DI + d;
    const float* up;
    int ustep;
    if (k < 2) { up = ubase + (size_t)(c * CL) * DI;          ustep = DI;  }
    else       { up = ubase + (size_t)(2303 - c * CL) * DI;   ustep = -DI; }

    for (int l0 = c * CL; l0 < (c + 1) * CL; l0 += 16) {
        float ur[16];
#pragma unroll
        for (int j = 0; j < 16; j++) ur[j] = up[(long)j * ustep];
        up += (long)16 * ustep;
#pragma unroll
        for (int q = 0; q < 4; q++) {
            float4 dv = dp[q];
            float dvv[4] = {dv.x, dv.y, dv.z, dv.w};
#pragma unroll
            for (int jj = 0; jj < 4; jj++) {
                int j = q * 4 + jj;
                float delta = dvv[jj];
                float4 Bv = Bq[j * 4];
                float4 Cv = Cq[j * 4];
                float du = delta * ur[j];
                float dA;
                dA = ex2(delta * a2[0]); h[0] = fmaf(h[0], dA, du * Bv.x);
                dA = ex2(delta * a2[1]); h[1] = fmaf(h[1], dA, du * Bv.y);
                dA = ex2(delta * a2[2]); h[2] = fmaf(h[2], dA, du * Bv.z);
                dA = ex2(delta * a2[3]); h[3] = fmaf(h[3], dA, du * Bv.w);
                float y = h[0] * Cv.x;
                y = fmaf(h[1], Cv.y, y);
                y = fmaf(h[2], Cv.z, y);
                y = fmaf(h[3], Cv.w, y);
                y += __shfl_xor_sync(0xffffffffu, y, 1);
                y += __shfl_xor_sync(0xffffffffu, y, 2);
                if (nq == jj) yk[q] = fmaf(Dd, ur[j], y);
            }
        }
        dp += 4;
        Bq += 64;
        Cq += 64;
#pragma unroll
        for (int q = 0; q < 4; q++)
            sy[q * 4 + nq][wid * 8 + dsub] = yk[q];
        __syncthreads();
        {
            int r = tid >> 4, cx = tid & 15;
            float* orow = &g_ysT[((size_t)bk * Ll + l0 + r) * DI + blockIdx.x * 64];
#pragma unroll
            for (int i = 0; i < 4; i++)
                orow[cx + 16 * i] = sy[r][cx + 16 * i];
        }
        __syncthreads();
    }
}

// ---------------- 6) cross-merge + LayerNorm + gate -> g_g (B,L,D) ----------
__global__ void merge_ln_gate(const float* __restrict__ lnw, const float* __restrict__ lnb) {
    int bp = blockIdx.x;
    int b = bp / Ll, p = bp % Ll;
    int d = threadIdx.x;
    int t1 = (p % 48) * 48 + (p / 48);
    size_t base = (size_t)b * Kk * Ll;
    float v = g_ysT[(base + 0 * Ll + p) * DI + d]
            + g_ysT[(base + 1 * Ll + t1) * DI + d]
            + g_ysT[(base + 2 * Ll + (2303 - p)) * DI + d]
            + g_ysT[(base + 3 * Ll + (2303 - t1)) * DI + d];

    float s = v, s2 = v * v;
#pragma unroll
    for (int o = 16; o > 0; o >>= 1) {
        s  += __shfl_xor_sync(0xffffffffu, s, o);
        s2 += __shfl_xor_sync(0xffffffffu, s2, o);
    }
    __shared__ float ws[12], ws2[12];
    __shared__ float mu_s, rstd_s;
    int wid = d >> 5, lid = d & 31;
    if (lid == 0) { ws[wid] = s; ws2[wid] = s2; }
    __syncthreads();
    if (d < 32) {
        float a  = (lid < 12) ? ws[lid]  : 0.f;
        float a2 = (lid < 12) ? ws2[lid] : 0.f;
#pragma unroll
        for (int o = 16; o > 0; o >>= 1) {
            a  += __shfl_xor_sync(0xffffffffu, a, o);
            a2 += __shfl_xor_sync(0xffffffffu, a2, o);
        }
        if (lid == 0) {
            float mu = a * (1.0f / DI);
            float var = a2 * (1.0f / DI) - mu * mu;
            mu_s = mu;
            rstd_s = rsqrtf(var + 1e-5f);
        }
    }
    __syncthreads();
    float nv = (v - mu_s) * rstd_s * lnw[d] + lnb[d];
    g_g[((size_t)b * Ll + p) * DI + d] = nv * g_z1t[((size_t)b * Ll + p) * DI + d];
}

// ---------------- 7) out_proj GEMM 64x128x(K=384), 8x4/thread, FFMA2 --------
__global__ __launch_bounds__(256) void gemm_outproj(const float* __restrict__ W2,
                                                    float* __restrict__ out) {
    __shared__ float As[16][68];
    __shared__ float Bs[16][132];
    int b = blockIdx.z;
    int mBase = blockIdx.y * 64;
    int nBase = blockIdx.x * 128;
    int tid = threadIdx.x;
    int tm = (tid >> 5) * 8;
    int tn4 = (tid & 31) * 4;

    unsigned long long acc2[8][2];
#pragma unroll
    for (int i = 0; i < 8; i++) { acc2[i][0] = 0ULL; acc2[i][1] = 0ULL; }

    for (int k0 = 0; k0 < DI; k0 += 16) {
#pragma unroll
        for (int t = 0; t < 4; t++) {
            int i = tid + t * 256;
            int r = i >> 4, c = i & 15;
            As[c][r] = W2[(mBase + r) * DI + k0 + c];
        }
#pragma unroll
        for (int t = 0; t < 2; t++) {
            int i = tid + t * 256;
            int n = i >> 2, kq = (i & 3) * 4;
            float4 v = *reinterpret_cast<const float4*>(
                &g_g[((size_t)b * Ll + nBase + n) * DI + k0 + kq]);
            Bs[kq][n] = v.x; Bs[kq + 1][n] = v.y;
            Bs[kq + 2][n] = v.z; Bs[kq + 3][n] = v.w;
        }
        __syncthreads();
#pragma unroll
        for (int kk = 0; kk < 16; kk++) {
            float4 a0 = *reinterpret_cast<const float4*>(&As[kk][tm]);
            float4 a1 = *reinterpret_cast<const float4*>(&As[kk][tm + 4]);
            ulonglong2 bq0 = *reinterpret_cast<const ulonglong2*>(&Bs[kk][tn4]);
            unsigned long long ap[8];
            ap[0] = pack2(a0.x, a0.x); ap[1] = pack2(a0.y, a0.y);
            ap[2] = pack2(a0.z, a0.z); ap[3] = pack2(a0.w, a0.w);
            ap[4] = pack2(a1.x, a1.x); ap[5] = pack2(a1.y, a1.y);
            ap[6] = pack2(a1.z, a1.z); ap[7] = pack2(a1.w, a1.w);
#pragma unroll
            for (int i = 0; i < 8; i++) {
                ffma2(acc2[i][0], ap[i], bq0.x);
                ffma2(acc2[i][1], ap[i], bq0.y);
            }
        }
        __syncthreads();
    }
#pragma unroll
    for (int i = 0; i < 8; i++) {
        float acc[4];
        unpack2(acc2[i][0], acc[0], acc[1]);
        unpack2(acc2[i][1], acc[2], acc[3]);
        int o = mBase + tm + i;
        float* row = &out[((size_t)b * DM + o) * Ll + nBase];
        *reinterpret_cast<float4*>(&row[tn4]) =
            make_float4(acc[0], acc[1], acc[2], acc[3]);
    }
}

extern "C" void kernel_launch(void* const* d_in, const int* in_sizes, int n_in,
                              void* d_out, int out_size) {
    const float* x     = (const float*)d_in[0];
    const float* inw   = (const float*)d_in[1];
    const float* convw = (const float*)d_in[2];
    const float* convb = (const float*)d_in[3];
    const float* xpw   = (const float*)d_in[4];
    const float* dtw   = (const float*)d_in[5];
    const float* dtb   = (const float*)d_in[6];
    const float* alogs = (const float*)d_in[7];
    const float* ds    = (const float*)d_in[8];
    const float* lnw   = (const float*)d_in[9];
    const float* lnb   = (const float*)d_in[10];
    const float* outw  = (const float*)d_in[11];
    float* out = (float*)d_out;

    gemm_inproj<<<dim3(9, 12, 4), 256>>>(inw, x);
    conv_dw<<<dim3(48, 24, 4), 256>>>(convw, convb);
    xdbl_kernel<<<dim3(36, 16), 256>>>(xpw);
    delta_kernel<<<dim3(144, 16), 384>>>(dtw, dtb);
    scan_passA<<<dim3(6, 16, Gc), 256>>>(alogs);
    scan_fixup<<<384, 256>>>();
    scan_passB<<<dim3(6, 16, Gc), 256>>>(alogs, ds);
    merge_ln_gate<<<Bb * Ll, 384>>>(lnw, lnb);
    gemm_outproj<<<dim3(18, 3, 4), 256>>>(outw, out);
}

// round 14
// speedup vs baseline: 1.5062x; 1.5062x over previous
#include <cuda_runtime.h>
#include <math.h>

#define Bb 4
#define DM 192
#define DI 384
#define Hh 48
#define Ww 48
#define Ll 2304
#define Kk 4
#define Nn 16
#define Rr 12
#define Cc 44   // R + 2N
#define Gc 16   // scan chunks
#define CL 144  // chunk length = Ll/Gc (multiple of 48)

// ---------------- scratch (static __device__, no allocation) ----------------
__device__ float g_xc  [(size_t)Bb*DI*Ll];        // (B, D, L)  pre-conv x branch
__device__ float g_xcT [(size_t)Bb*Ll*DI];        // (B, L, D)  post conv+gelu (row-major order)
__device__ float g_u1  [(size_t)Bb*Ll*DI];        // (B, L1,D)  same, column-major scan order
__device__ float g_z1t [(size_t)Bb*Ll*DI];        // (B, L, D)  gelu(z)
__device__ float g_dts [(size_t)Bb*Kk*Ll*Rr];     // (B,K,L,12)
__device__ float g_B   [(size_t)Bb*Kk*Ll*Nn];     // (B,K,L,N)
__device__ float g_C   [(size_t)Bb*Kk*Ll*Nn];     // (B,K,L,N)
__device__ float g_dlt [(size_t)Bb*Kk*DI*Ll];     // (B,K,D,L)  softplus delta
__device__ float g_ysT [(size_t)Bb*Kk*Ll*DI];     // (B,K,L,D)  scan outputs (+D*u)
__device__ float g_g   [(size_t)Bb*Ll*DI];        // (B, L, D)  gated, pre out_proj
__device__ float2 g_PF [(size_t)Bb*Kk*DI*Nn*Gc];  // (bk,d,n,c) chunk (P, F)
__device__ float g_hin [(size_t)Bb*Kk*DI*Nn*Gc];  // (bk,d,n,c) chunk incoming h

__device__ __forceinline__ float gelu_exact(float x) {
    return 0.5f * x * (1.0f + erff(x * 0.7071067811865476f));
}

// raw MUFU.EX2 (exp2f without fast-math lowers to a slow software sequence)
__device__ __forceinline__ float ex2(float x) {
    float y;
    asm("ex2.approx.f32 %0, %1;" : "=f"(y) : "f"(x));
    return y;
}

// ---- packed fp32x2 helpers (sm_10x FFMA2) ----
__device__ __forceinline__ unsigned long long pack2(float lo, float hi) {
    unsigned long long r;
    asm("mov.b64 %0, {%1, %2};" : "=l"(r) : "f"(lo), "f"(hi));
    return r;
}
__device__ __forceinline__ void unpack2(unsigned long long v, float& lo, float& hi) {
    asm("mov.b64 {%0, %1}, %2;" : "=f"(lo), "=f"(hi) : "l"(v));
}
__device__ __forceinline__ void ffma2(unsigned long long& d, unsigned long long a,
                                      unsigned long long b) {
    asm("fma.rn.f32x2 %0, %1, %2, %3;" : "=l"(d) : "l"(a), "l"(b), "l"(d));
}

// ---------------- 1) in_proj GEMM 64x256x(K=192), 8x8/thread, FFMA2 ---------
__global__ __launch_bounds__(256) void gemm_inproj(const float* __restrict__ W,
                                                   const float* __restrict__ x) {
    __shared__ float As[16][68];
    __shared__ float Bs[16][260];
    int b = blockIdx.z;
    int mBase = blockIdx.y * 64;
    int nBase = blockIdx.x * 256;
    int tid = threadIdx.x;
    int tm = (tid >> 5) * 8;
    int tn4 = (tid & 31) * 4;

    unsigned long long acc2[8][4];
#pragma unroll
    for (int i = 0; i < 8; i++)
#pragma unroll
        for (int j = 0; j < 4; j++) acc2[i][j] = 0ULL;

    for (int k0 = 0; k0 < 192; k0 += 16) {
#pragma unroll
        for (int t = 0; t < 4; t++) {
            int i = tid + t * 256;
            int r = i >> 4, c = i & 15;
            As[c][r] = W[(mBase + r) * 192 + k0 + c];
        }
#pragma unroll
        for (int t = 0; t < 16; t++) {
            int i = tid + t * 256;
            int r = i >> 8, n = i & 255;
            Bs[r][n] = x[((size_t)b * 192 + (k0 + r)) * Ll + nBase + n];
        }
        __syncthreads();
#pragma unroll
        for (int kk = 0; kk < 16; kk++) {
            float4 a0 = *reinterpret_cast<const float4*>(&As[kk][tm]);
            float4 a1 = *reinterpret_cast<const float4*>(&As[kk][tm + 4]);
            ulonglong2 bq0 = *reinterpret_cast<const ulonglong2*>(&Bs[kk][tn4]);
            ulonglong2 bq1 = *reinterpret_cast<const ulonglong2*>(&Bs[kk][tn4 + 128]);
            unsigned long long ap[8];
            ap[0] = pack2(a0.x, a0.x); ap[1] = pack2(a0.y, a0.y);
            ap[2] = pack2(a0.z, a0.z); ap[3] = pack2(a0.w, a0.w);
            ap[4] = pack2(a1.x, a1.x); ap[5] = pack2(a1.y, a1.y);
            ap[6] = pack2(a1.z, a1.z); ap[7] = pack2(a1.w, a1.w);
            unsigned long long bp[4] = {bq0.x, bq0.y, bq1.x, bq1.y};
#pragma unroll
            for (int i = 0; i < 8; i++)
#pragma unroll
                for (int j = 0; j < 4; j++) ffma2(acc2[i][j], ap[i], bp[j]);
        }
        __syncthreads();
    }
    float acc[8][8];
#pragma unroll
    for (int i = 0; i < 8; i++) {
        unpack2(acc2[i][0], acc[i][0], acc[i][1]);
        unpack2(acc2[i][1], acc[i][2], acc[i][3]);
        unpack2(acc2[i][2], acc[i][4], acc[i][5]);
        unpack2(acc2[i][3], acc[i][6], acc[i][7]);
    }
    if (mBase < DI) {   // x branch -> g_xc (B, D, L)
#pragma unroll
        for (int i = 0; i < 8; i++) {
            int o = mBase + tm + i;
            float* row = &g_xc[((size_t)b * DI + o) * Ll + nBase];
            *reinterpret_cast<float4*>(&row[tn4]) =
                make_float4(acc[i][0], acc[i][1], acc[i][2], acc[i][3]);
            *reinterpret_cast<float4*>(&row[tn4 + 128]) =
                make_float4(acc[i][4], acc[i][5], acc[i][6], acc[i][7]);
        }
    } else {            // z branch -> gelu -> g_z1t (B, L, D)
        int oz = mBase - DI + tm;
#pragma unroll
        for (int j = 0; j < 8; j++) {
            int l = nBase + ((j < 4) ? (tn4 + j) : (128 + tn4 + j - 4));
            float* row = &g_z1t[((size_t)b * Ll + l) * DI + oz];
            *reinterpret_cast<float4*>(row) = make_float4(
                gelu_exact(acc[0][j]), gelu_exact(acc[1][j]),
                gelu_exact(acc[2][j]), gelu_exact(acc[3][j]));
            *reinterpret_cast<float4*>(row + 4) = make_float4(
                gelu_exact(acc[4][j]), gelu_exact(acc[5][j]),
                gelu_exact(acc[6][j]), gelu_exact(acc[7][j]));
        }
    }
}

// ---------------- 2) depthwise 3x3 conv, row-tiled, coalesced IO -------------
__global__ void conv_dw(const float* __restrict__ cw, const float* __restrict__ cb) {
    __shared__ float s[16][145];
    int b = blockIdx.z;
    int d0 = blockIdx.y * 16;
    int h = blockIdx.x;
    int t = threadIdx.x;  // 256

    for (int i = t; i < 16 * 144; i += 256) {
        int d = i / 144, j = i % 144;
        int r = j / 48;
        int hh = h + r - 1;
        float v = 0.f;
        if (hh >= 0 && hh < 48)
            v = g_xc[((size_t)b * DI + d0 + d) * Ll + hh * 48 + (j - r * 48)];
        s[d][j] = v;
    }
    __syncthreads();

    int d = t & 15, w0 = t >> 4;
    float wr[9];
#pragma unroll
    for (int i = 0; i < 9; i++) wr[i] = cw[(d0 + d) * 9 + i];
    float bias = cb[d0 + d];

#pragma unroll
    for (int wi = 0; wi < 3; wi++) {
        int w = w0 + wi * 16;
        float acc = bias;
#pragma unroll
        for (int dh = 0; dh < 3; dh++)
#pragma unroll
            for (int dw = 0; dw < 3; dw++) {
                int ww = w + dw - 1;
                if (ww >= 0 && ww < 48)
                    acc = fmaf(wr[dh * 3 + dw], s[d][dh * 48 + ww], acc);
            }
        float v = gelu_exact(acc);
        g_xcT[((size_t)b * Ll + h * 48 + w) * DI + d0 + d] = v;
        g_u1 [((size_t)b * Ll + w * 48 + h) * DI + d0 + d] = v;
    }
}

// ---------------- 3) x_dbl GEMM: (44 x 2304) = W_k(44x384) @ xs[bk], FFMA2 ---
__global__ void xdbl_kernel(const float* __restrict__ xpw) {
    __shared__ float Ws[32][49];
    __shared__ float Xs[32][68];
    int bk = blockIdx.y;
    int b = bk >> 2, k = bk & 3;
    int l0 = blockIdx.x * 64;
    int tid = threadIdx.x;
    int tc = (tid >> 4) * 3;
    int tl = (tid & 15) * 4;

    const float* ubase = ((k & 1) ? g_u1 : g_xcT) + (size_t)b * Ll * DI;

    unsigned long long acc2[3][2];
#pragma unroll
    for (int i = 0; i < 3; i++) { acc2[i][0] = 0ULL; acc2[i][1] = 0ULL; }

    if (tid < 128) {
        int kd = tid & 31, c = 44 + (tid >> 5);
        Ws[kd][c] = 0.f;
    }
    __syncthreads();

    for (int k0 = 0; k0 < DI; k0 += 32) {
        for (int i = tid; i < 44 * 32; i += 256) {
            int c = i >> 5, kd = i & 31;
            Ws[kd][c] = xpw[((size_t)(k * Cc + c)) * DI + k0 + kd];
        }
#pragma unroll
        for (int t = 0; t < 2; t++) {
            int q = tid + t * 256;
            int l = q >> 3, kq = (q & 7) * 4;
            int row = (k < 2) ? (l0 + l) : (2303 - (l0 + l));
            float4 v = *reinterpret_cast<const float4*>(&ubase[(size_t)row * DI + k0 + kq]);
            Xs[kq][l] = v.x; Xs[kq + 1][l] = v.y;
            Xs[kq + 2][l] = v.z; Xs[kq + 3][l] = v.w;
        }
        __syncthreads();
#pragma unroll
        for (int kd = 0; kd < 32; kd++) {
            unsigned long long ap0 = pack2(Ws[kd][tc], Ws[kd][tc]);
            unsigned long long ap1 = pack2(Ws[kd][tc + 1], Ws[kd][tc + 1]);
            unsigned long long ap2 = pack2(Ws[kd][tc + 2], Ws[kd][tc + 2]);
            ulonglong2 bq = *reinterpret_cast<const ulonglong2*>(&Xs[kd][tl]);
            ffma2(acc2[0][0], ap0, bq.x); ffma2(acc2[0][1], ap0, bq.y);
            ffma2(acc2[1][0], ap1, bq.x); ffma2(acc2[1][1], ap1, bq.y);
            ffma2(acc2[2][0], ap2, bq.x); ffma2(acc2[2][1], ap2, bq.y);
        }
        __syncthreads();
    }
    float acc[3][4];
#pragma unroll
    for (int r = 0; r < 3; r++) {
        unpack2(acc2[r][0], acc[r][0], acc[r][1]);
        unpack2(acc2[r][1], acc[r][2], acc[r][3]);
    }
#pragma unroll
    for (int r = 0; r < 3; r++) {
        int c = tc + r;
        if (c < 12) {
#pragma unroll
            for (int j = 0; j < 4; j++)
                g_dts[((size_t)bk * Ll + l0 + tl + j) * Rr + c] = acc[r][j];
        } else if (c < 28) {
#pragma unroll
            for (int j = 0; j < 4; j++)
                g_B[((size_t)bk * Ll + l0 + tl + j) * Nn + (c - 12)] = acc[r][j];
        } else if (c < Cc) {
#pragma unroll
            for (int j = 0; j < 4; j++)
                g_C[((size_t)bk * Ll + l0 + tl + j) * Nn + (c - 28)] = acc[r][j];
        }
    }
}

// ---------------- 4) delta = softplus(dtw @ dts + bias) -> (bk, d, L) --------
__global__ void delta_kernel(const float* __restrict__ dtw, const float* __restrict__ dtb) {
    __shared__ float dts_s[16][12];
    __shared__ float stage[384 * 16 + 224];
    int bk = blockIdx.y;
    int k = bk & 3;
    int l0 = blockIdx.x * 16;
    int d = threadIdx.x;   // 384 threads

    if (threadIdx.x < 192) {
        int l = threadIdx.x / 12, r = threadIdx.x % 12;
        dts_s[l][r] = g_dts[((size_t)bk * Ll + l0 + l) * Rr + r];
    }
    float w[12];
    {
        const float4* wp = reinterpret_cast<const float4*>(dtw + ((size_t)k * DI + d) * Rr);
        float4 a = wp[0], bq = wp[1], cq = wp[2];
        w[0]=a.x; w[1]=a.y; w[2]=a.z; w[3]=a.w;
        w[4]=bq.x; w[5]=bq.y; w[6]=bq.z; w[7]=bq.w;
        w[8]=cq.x; w[9]=cq.y; w[10]=cq.z; w[11]=cq.w;
    }
    float bias = dtb[k * DI + d];
    __syncthreads();

#pragma unroll
    for (int l = 0; l < 16; l++) {
        float acc = bias;
#pragma unroll
        for (int r = 0; r < Rr; r++) acc = fmaf(w[r], dts_s[l][r], acc);
        float sp = (acc > 15.f) ? acc : __logf(1.f + __expf(acc));
        stage[d * 16 + l + (d >> 1)] = sp;
    }
    __syncthreads();
    int lw = threadIdx.x & 15;
    int dw0 = threadIdx.x >> 4;
#pragma unroll
    for (int i = 0; i < 16; i++) {
        int dd = dw0 + 24 * i;
        g_dlt[((size_t)bk * DI + dd) * Ll + l0 + lw] = stage[dd * 16 + lw + (dd >> 1)];
    }
}

// ---------------- 5a) scan pass A: 4-lane x 4-state; (P, F) per chunk --------
__global__ void scan_passA(const float* __restrict__ Alogs) {
    int bk = blockIdx.y;
    int b = bk >> 2, k = bk & 3;
    int wid = threadIdx.x >> 5, lane = threadIdx.x & 31;
    int dsub = lane >> 2, nq = lane & 3;
    int d = blockIdx.x * 64 + wid * 8 + dsub;
    int c = blockIdx.z;

    float a2[4], h[4] = {0.f, 0.f, 0.f, 0.f}, P[4] = {1.f, 1.f, 1.f, 1.f};
#pragma unroll
    for (int i = 0; i < 4; i++)
        a2[i] = -__expf(Alogs[((size_t)k * DI + d) * Nn + 4 * nq + i]) * 1.4426950408889634f;

    const float4* dp = reinterpret_cast<const float4*>(g_dlt + ((size_t)bk * DI + d) * Ll + c * CL);
    const float4* Bq = reinterpret_cast<const float4*>(g_B + ((size_t)bk * Ll + c * CL) * Nn + 4 * nq);
    const float* ubase = ((k & 1) ? g_u1 : g_xcT) + (size_t)b * Ll * DI + d;
    const float* up;
    int ustep;
    if (k < 2) { up = ubase + (size_t)(c * CL) * DI;          ustep = DI;  }
    else       { up = ubase + (size_t)(2303 - c * CL) * DI;   ustep = -DI; }

    for (int q = 0; q < CL / 4; q++) {
        float4 dv = *dp++;
        float dvv[4] = {dv.x, dv.y, dv.z, dv.w};
#pragma unroll
        for (int jj = 0; jj < 4; jj++) {
            float delta = dvv[jj];
            float u = *up; up += ustep;
            float4 Bv = *Bq; Bq += 4;
            float du = delta * u;
            float dA;
            dA = ex2(delta * a2[0]); h[0] = fmaf(h[0], dA, du * Bv.x); P[0] *= dA;
            dA = ex2(delta * a2[1]); h[1] = fmaf(h[1], dA, du * Bv.y); P[1] *= dA;
            dA = ex2(delta * a2[2]); h[2] = fmaf(h[2], dA, du * Bv.z); P[2] *= dA;
            dA = ex2(delta * a2[3]); h[3] = fmaf(h[3], dA, du * Bv.w); P[3] *= dA;
        }
    }
#pragma unroll
    for (int i = 0; i < 4; i++)
        g_PF[(((size_t)bk * DI + d) * Nn + 4 * nq + i) * Gc + c] = make_float2(P[i], h[i]);
}

// ---------------- 5b) fixup: sequential combine over chunks ------------------
__global__ void scan_fixup() {
    int t = blockIdx.x * 256 + threadIdx.x;   // over 16*384*16 = 98304
    size_t base = (size_t)t * Gc;
    float h = 0.f;
#pragma unroll
    for (int c = 0; c < Gc; c++) {
        g_hin[base + c] = h;
        float2 pf = g_PF[base + c];
        h = fmaf(pf.x, h, pf.y);
    }
}

// ---------------- 5c) scan pass B: 4-lane x 4-state, seeded ------------------
__global__ void scan_passB(const float* __restrict__ Alogs, const float* __restrict__ Ds) {
    __shared__ float sy[16][65];
    int bk = blockIdx.y;
    int b = bk >> 2, k = bk & 3;
    int tid = threadIdx.x;
    int wid = tid >> 5, lane = tid & 31;
    int dsub = lane >> 2, nq = lane & 3;
    int d = blockIdx.x * 64 + wid * 8 + dsub;
    int c = blockIdx.z;

    float a2[4], h[4], yk[4];
#pragma unroll
    for (int i = 0; i < 4; i++) {
        a2[i] = -__expf(Alogs[((size_t)k * DI + d) * Nn + 4 * nq + i]) * 1.4426950408889634f;
        h[i] = g_hin[(((size_t)bk * DI + d) * Nn + 4 * nq + i) * Gc + c];
    }
    float Dd = Ds[k * DI + d];

    const float4* dp = reinterpret_cast<const float4*>(g_dlt + ((size_t)bk * DI + d) * Ll + c * CL);
    const float4* Bq = reinterpret_cast<const float4*>(g_B + ((size_t)bk * Ll + c * CL) * Nn + 4 * nq);
    const float4* Cq = reinterpret_cast<const float4*>(g_C + ((size_t)bk * Ll + c * CL) * Nn + 4 * nq);
    const float* ubase = ((k & 1) ? g_u1 : g_xcT) + (size_t)b * Ll * DI + d;
    const float* up;
    int ustep;
    if (k < 2) { up = ubase + (size_t)(c * CL) * DI;          ustep = DI;  }
    else       { up = ubase + (size_t)(2303 - c * CL) * DI;   ustep = -DI; }

    for (int l0 = c * CL; l0 < (c + 1) * CL; l0 += 16) {
#pragma unroll
        for (int q = 0; q < 4; q++) {
            float4 dv = *dp++;
            float dvv[4] = {dv.x, dv.y, dv.z, dv.w};
#pragma unroll
            for (int jj = 0; jj < 4; jj++) {
                float delta = dvv[jj];
                float u = *up; up += ustep;
                float4 Bv = *Bq; Bq += 4;
                float4 Cv = *Cq; Cq += 4;
                float du = delta * u;
                float dA;
                dA = ex2(delta * a2[0]); h[0] = fmaf(h[0], dA, du * Bv.x);
                dA = ex2(delta * a2[1]); h[1] = fmaf(h[1], dA, du * Bv.y);
                dA = ex2(delta * a2[2]); h[2] = fmaf(h[2], dA, du * Bv.z);
                dA = ex2(delta * a2[3]); h[3] = fmaf(h[3], dA, du * Bv.w);
                float y = h[0] * Cv.x;
                y = fmaf(h[1], Cv.y, y);
                y = fmaf(h[2], Cv.z, y);
                y = fmaf(h[3], Cv.w, y);
                y += __shfl_xor_sync(0xffffffffu, y, 1);
                y += __shfl_xor_sync(0xffffffffu, y, 2);
                if (nq == jj) yk[q] = fmaf(Dd, u, y);
            }
        }
#pragma unroll
        for (int q = 0; q < 4; q++)
            sy[q * 4 + nq][wid * 8 + dsub] = yk[q];
        __syncthreads();
        {
            int r = tid >> 4, cx = tid & 15;
            float* orow = &g_ysT[((size_t)bk * Ll + l0 + r) * DI + blockIdx.x * 64];
#pragma unroll
            for (int i = 0; i < 4; i++)
                orow[cx + 16 * i] = sy[r][cx + 16 * i];
        }
        __syncthreads();
    }
}

// ---------------- 6) cross-merge + LayerNorm + gate -> g_g (B,L,D) ----------
__global__ void merge_ln_gate(const float* __restrict__ lnw, const float* __restrict__ lnb) {
    int bp = blockIdx.x;
    int b = bp / Ll, p = bp % Ll;
    int d = threadIdx.x;
    int t1 = (p % 48) * 48 + (p / 48);
    size_t base = (size_t)b * Kk * Ll;
    float v = g_ysT[(base + 0 * Ll + p) * DI + d]
            + g_ysT[(base + 1 * Ll + t1) * DI + d]
            + g_ysT[(base + 2 * Ll + (2303 - p)) * DI + d]
            + g_ysT[(base + 3 * Ll + (2303 - t1)) * DI + d];

    float s = v, s2 = v * v;
#pragma unroll
    for (int o = 16; o > 0; o >>= 1) {
        s  += __shfl_xor_sync(0xffffffffu, s, o);
        s2 += __shfl_xor_sync(0xffffffffu, s2, o);
    }
    __shared__ float ws[12], ws2[12];
    __shared__ float mu_s, rstd_s;
    int wid = d >> 5, lid = d & 31;
    if (lid == 0) { ws[wid] = s; ws2[wid] = s2; }
    __syncthreads();
    if (d < 32) {
        float a  = (lid < 12) ? ws[lid]  : 0.f;
        float a2 = (lid < 12) ? ws2[lid] : 0.f;
#pragma unroll
        for (int o = 16; o > 0; o >>= 1) {
            a  += __shfl_xor_sync(0xffffffffu, a, o);
            a2 += __shfl_xor_sync(0xffffffffu, a2, o);
        }
        if (lid == 0) {
            float mu = a * (1.0f / DI);
            float var = a2 * (1.0f / DI) - mu * mu;
            mu_s = mu;
            rstd_s = rsqrtf(var + 1e-5f);
        }
    }
    __syncthreads();
    float nv = (v - mu_s) * rstd_s * lnw[d] + lnb[d];
    g_g[((size_t)b * Ll + p) * DI + d] = nv * g_z1t[((size_t)b * Ll + p) * DI + d];
}

// ---------------- 7) out_proj GEMM 64x128x(K=384), 8x4/thread, FFMA2 --------
__global__ __launch_bounds__(256) void gemm_outproj(const float* __restrict__ W2,
                                                    float* __restrict__ out) {
    __shared__ float As[16][68];
    __shared__ float Bs[16][132];
    int b = blockIdx.z;
    int mBase = blockIdx.y * 64;
    int nBase = blockIdx.x * 128;
    int tid = threadIdx.x;
    int tm = (tid >> 5) * 8;
    int tn4 = (tid & 31) * 4;

    unsigned long long acc2[8][2];
#pragma unroll
    for (int i = 0; i < 8; i++) { acc2[i][0] = 0ULL; acc2[i][1] = 0ULL; }

    for (int k0 = 0; k0 < DI; k0 += 16) {
#pragma unroll
        for (int t = 0; t < 4; t++) {
            int i = tid + t * 256;
            int r = i >> 4, c = i & 15;
            As[c][r] = W2[(mBase + r) * DI + k0 + c];
        }
#pragma unroll
        for (int t = 0; t < 2; t++) {
            int i = tid + t * 256;
            int n = i >> 2, kq = (i & 3) * 4;
            float4 v = *reinterpret_cast<const float4*>(
                &g_g[((size_t)b * Ll + nBase + n) * DI + k0 + kq]);
            Bs[kq][n] = v.x; Bs[kq + 1][n] = v.y;
            Bs[kq + 2][n] = v.z; Bs[kq + 3][n] = v.w;
        }
        __syncthreads();
#pragma unroll
        for (int kk = 0; kk < 16; kk++) {
            float4 a0 = *reinterpret_cast<const float4*>(&As[kk][tm]);
            float4 a1 = *reinterpret_cast<const float4*>(&As[kk][tm + 4]);
            ulonglong2 bq0 = *reinterpret_cast<const ulonglong2*>(&Bs[kk][tn4]);
            unsigned long long ap[8];
            ap[0] = pack2(a0.x, a0.x); ap[1] = pack2(a0.y, a0.y);
            ap[2] = pack2(a0.z, a0.z); ap[3] = pack2(a0.w, a0.w);
            ap[4] = pack2(a1.x, a1.x); ap[5] = pack2(a1.y, a1.y);
            ap[6] = pack2(a1.z, a1.z); ap[7] = pack2(a1.w, a1.w);
#pragma unroll
            for (int i = 0; i < 8; i++) {
                ffma2(acc2[i][0], ap[i], bq0.x);
                ffma2(acc2[i][1], ap[i], bq0.y);
            }
        }
        __syncthreads();
    }
#pragma unroll
    for (int i = 0; i < 8; i++) {
        float acc[4];
        unpack2(acc2[i][0], acc[0], acc[1]);
        unpack2(acc2[i][1], acc[2], acc[3]);
        int o = mBase + tm + i;
        float* row = &out[((size_t)b * DM + o) * Ll + nBase];
        *reinterpret_cast<float4*>(&row[tn4]) =
            make_float4(acc[0], acc[1], acc[2], acc[3]);
    }
}

extern "C" void kernel_launch(void* const* d_in, const int* in_sizes, int n_in,
                              void* d_out, int out_size) {
    const float* x     = (const float*)d_in[0];
    const float* inw   = (const float*)d_in[1];
    const float* convw = (const float*)d_in[2];
    const float* convb = (const float*)d_in[3];
    const float* xpw   = (const float*)d_in[4];
    const float* dtw   = (const float*)d_in[5];
    const float* dtb   = (const float*)d_in[6];
    const float* alogs = (const float*)d_in[7];
    const float* ds    = (const float*)d_in[8];
    const float* lnw   = (const float*)d_in[9];
    const float* lnb   = (const float*)d_in[10];
    const float* outw  = (const float*)d_in[11];
    float* out = (float*)d_out;

    gemm_inproj<<<dim3(9, 12, 4), 256>>>(inw, x);
    conv_dw<<<dim3(48, 24, 4), 256>>>(convw, convb);
    xdbl_kernel<<<dim3(36, 16), 256>>>(xpw);
    delta_kernel<<<dim3(144, 16), 384>>>(dtw, dtb);
    scan_passA<<<dim3(6, 16, Gc), 256>>>(alogs);
    scan_fixup<<<384, 256>>>();
    scan_passB<<<dim3(6, 16, Gc), 256>>>(alogs, ds);
    merge_ln_gate<<<Bb * Ll, 384>>>(lnw, lnb);
    gemm_outproj<<<dim3(18, 3, 4), 256>>>(outw, out);
}